// round 9
// baseline (speedup 1.0000x reference)
#include <cuda_runtime.h>
#include <math.h>

typedef unsigned long long ull;

// ---- problem constants ----
#define BB  16
#define HH  384
#define WW  512
#define HPP 191
#define WPP 255
#define H2D 189
#define W2D 253
#define H3D 187
#define W3D 251
#define NPIX (H3D*W3D)   // 46937
#define NEGV (-1e30f)
#define THRESH_V 0.6f
#define KPICKS 128
#define CAP 5600
#define SP  260          // padded row stride (mult of 4)
#define PH  196          // padded plane height

// logit(0.6) = ln(1.5); filter band 0.01 >> winograd fp32 error (~1e-4)
#define LOGIT06 0.40546510810816444f
#define BAND    0.01f

// staging layout offsets (in ull)
#define W1OFF 0
#define W1N   135
#define W2OFF 135
#define W2N   720
#define W3OFF 855
#define W3N   2304
#define W3WOFF 3159
#define W3WN  3072
#define WTOT  6231

// ---- scratch (zero-initialized device globals) ----
__device__ __align__(16) float  g_pool[BB*10*PH*SP];
__device__ __align__(16) float  g_h2[BB*16*PH*SP];
__device__ __align__(16) ull    g_stage[WTOT];
__device__ int    g_cnt[BB];
__device__ int    g_wcnt;
__device__ int    g_work[BB*NPIX];      // packed (bb<<20)|(y<<10)|x
__device__ int    g_cand[BB*NPIX];      // packed (y<<16)|x
__device__ float  g_cand_sc[BB*NPIX];
__device__ float4 g_cand_reg[BB*NPIX];

// ---- packed oc-pair weights in constant memory (direct/exact paths) ----
__constant__ ull c_w1[W1N];    // [(c*9+k)*5  + q]
__constant__ ull c_w2[W2N];    // [(c*9+k)*8  + q]
__constant__ ull c_w3[W3N];    // [(c*9+k)*16 + q]

// ---- f32x2 helpers ----
__device__ __forceinline__ ull pack2(float lo, float hi){
    ull r; asm("mov.b64 %0, {%1, %2};" : "=l"(r) : "f"(lo), "f"(hi)); return r;
}
__device__ __forceinline__ void unpack2(ull v, float &lo, float &hi){
    asm("mov.b64 {%0, %1}, %2;" : "=f"(lo), "=f"(hi) : "l"(v));
}
__device__ __forceinline__ void fma2(ull &d, ull a, ull b){
    asm("fma.rn.f32x2 %0, %1, %2, %0;" : "+l"(d) : "l"(a), "l"(b));
}

// ============================================================
// K0: pack weights (direct oc-pair + winograd) and zero counters
// ============================================================
__global__ void k0_pack(const float* __restrict__ w1,
                        const float* __restrict__ w2,
                        const float* __restrict__ w3)
{
    int tid = threadIdx.x;
    if (tid < BB) g_cnt[tid] = 0;
    if (tid == 0) g_wcnt = 0;
    for (int i = tid; i < W1N; i += 256){
        int ck = i / 5, q = i % 5;
        g_stage[W1OFF + i] = pack2(w1[(2*q)*27 + ck], w1[(2*q+1)*27 + ck]);
    }
    for (int i = tid; i < W2N; i += 256){
        int ck = i >> 3, q = i & 7;
        g_stage[W2OFF + i] = pack2(w2[(2*q)*90 + ck], w2[(2*q+1)*90 + ck]);
    }
    for (int i = tid; i < W3N; i += 256){
        int ck = i >> 4, q = i & 15;
        g_stage[W3OFF + i] = pack2(w3[(2*q)*144 + ck], w3[(2*q+1)*144 + ck]);
    }
    // winograd F(2,3) conv3 weights: g' = (g0, (g0+g1+g2)/2, (g0-g1+g2)/2, g2)
    // layout: [((c*3+ky)*4 + j)*16 + q]
    for (int i = tid; i < W3WN; i += 256){
        int q = i & 15;
        int t = i >> 4;
        int j = t & 3;
        int t2 = t >> 2;
        int ky = t2 % 3;
        int c  = t2 / 3;
        float v[2];
#pragma unroll
        for (int s = 0; s < 2; s++){
            int oc = 2*q + s;
            const float* g = w3 + oc*144 + c*9 + ky*3;
            float g0 = g[0], g1 = g[1], g2 = g[2];
            v[s] = (j == 0) ? g0
                 : (j == 1) ? 0.5f*(g0 + g1 + g2)
                 : (j == 2) ? 0.5f*(g0 - g1 + g2)
                 : g2;
        }
        g_stage[W3WOFF + i] = pack2(v[0], v[1]);
    }
}

// ============================================================
// K1: normalize + conv1(3x3,3->10) + PReLU + maxpool2x2  [R5]
// ============================================================
__global__ __launch_bounds__(256) void k1_conv1_pool(const float* __restrict__ im,
                              const float* __restrict__ b,
                              const float* __restrict__ p)
{
    __shared__ float sb[10], sp[10];
    int tid = threadIdx.y * 32 + threadIdx.x;
    if (tid < 10){ sb[tid] = b[tid]; sp[tid] = p[tid]; }
    __syncthreads();

    int ox = blockIdx.x * 32 + threadIdx.x;
    int oy = blockIdx.y * 8  + threadIdx.y;
    int bb = blockIdx.z;
    if (ox >= WPP || oy >= HPP) return;

    ull acc[4][5];
#pragma unroll
    for (int q = 0; q < 5; q++){
        ull bi = pack2(sb[2*q], sb[2*q+1]);
        acc[0][q] = bi; acc[1][q] = bi; acc[2][q] = bi; acc[3][q] = bi;
    }

#pragma unroll
    for (int c = 0; c < 3; c++){
        const float* base = im + ((bb*3 + c)*HH + 2*oy)*WW + 2*ox;
        ull du[4][4];
#pragma unroll
        for (int r = 0; r < 4; r++){
            float2 u01 = *reinterpret_cast<const float2*>(base + r*WW);
            float2 u23 = *reinterpret_cast<const float2*>(base + r*WW + 2);
            float v0 = (u01.x - 127.5f)*0.0078125f;
            float v1 = (u01.y - 127.5f)*0.0078125f;
            float v2 = (u23.x - 127.5f)*0.0078125f;
            float v3 = (u23.y - 127.5f)*0.0078125f;
            du[r][0] = pack2(v0,v0); du[r][1] = pack2(v1,v1);
            du[r][2] = pack2(v2,v2); du[r][3] = pack2(v3,v3);
        }
#pragma unroll
        for (int ky = 0; ky < 3; ky++)
#pragma unroll
        for (int kx = 0; kx < 3; kx++){
            const ull* wq = &c_w1[(c*9 + ky*3 + kx)*5];
#pragma unroll
            for (int q = 0; q < 5; q++){
                ull wv = wq[q];
                fma2(acc[0][q], du[ky  ][kx  ], wv);
                fma2(acc[1][q], du[ky  ][kx+1], wv);
                fma2(acc[2][q], du[ky+1][kx  ], wv);
                fma2(acc[3][q], du[ky+1][kx+1], wv);
            }
        }
    }
#pragma unroll
    for (int q = 0; q < 5; q++){
        float h[4][2];
#pragma unroll
        for (int pp = 0; pp < 4; pp++) unpack2(acc[pp][q], h[pp][0], h[pp][1]);
#pragma unroll
        for (int s = 0; s < 2; s++){
            int oc = 2*q + s;
            float al = sp[oc];
            float m = -INFINITY;
#pragma unroll
            for (int pp = 0; pp < 4; pp++){
                float v = h[pp][s];
                v = v > 0.f ? v : al*v;
                m = fmaxf(m, v);
            }
            g_pool[((bb*10 + oc)*PH + oy)*SP + ox] = m;
        }
    }
}

// ============================================================
// K2: conv2(3x3,10->16) + PReLU, 4 px/thread  [R5, exact]
// ============================================================
__global__ __launch_bounds__(256) void k2_conv2(const float* __restrict__ b,
                         const float* __restrict__ p)
{
    __shared__ float sb[16], sp[16];
    int tid = threadIdx.y * 32 + threadIdx.x;
    if (tid < 16){ sb[tid] = b[tid]; sp[tid] = p[tid]; }
    __syncthreads();

    int x0 = blockIdx.x * 128 + threadIdx.x * 4;
    int oy = blockIdx.y * 8   + threadIdx.y;
    int bb = blockIdx.z;

    ull acc[4][8];
#pragma unroll
    for (int q = 0; q < 8; q++){
        ull bi = pack2(sb[2*q], sb[2*q+1]);
        acc[0][q] = bi; acc[1][q] = bi; acc[2][q] = bi; acc[3][q] = bi;
    }

    for (int c = 0; c < 10; c++){
        const float* base = g_pool + ((bb*10 + c)*PH + oy)*SP + x0;
        ull du[3][6];
#pragma unroll
        for (int r = 0; r < 3; r++){
            float4 a4 = *reinterpret_cast<const float4*>(base + r*SP);
            float2 b2 = *reinterpret_cast<const float2*>(base + r*SP + 4);
            du[r][0] = pack2(a4.x,a4.x); du[r][1] = pack2(a4.y,a4.y);
            du[r][2] = pack2(a4.z,a4.z); du[r][3] = pack2(a4.w,a4.w);
            du[r][4] = pack2(b2.x,b2.x); du[r][5] = pack2(b2.y,b2.y);
        }
#pragma unroll
        for (int ky = 0; ky < 3; ky++)
#pragma unroll
        for (int kx = 0; kx < 3; kx++){
            const ull* wq = &c_w2[(c*9 + ky*3 + kx)*8];
#pragma unroll
            for (int q = 0; q < 8; q++){
                ull wv = wq[q];
#pragma unroll
                for (int pp = 0; pp < 4; pp++)
                    fma2(acc[pp][q], du[ky][kx+pp], wv);
            }
        }
    }
#pragma unroll
    for (int q = 0; q < 8; q++){
        float v[4][2];
#pragma unroll
        for (int pp = 0; pp < 4; pp++) unpack2(acc[pp][q], v[pp][0], v[pp][1]);
#pragma unroll
        for (int s = 0; s < 2; s++){
            int oc = 2*q + s;
            float al = sp[oc];
            float4 o;
            float t0 = v[0][s]; o.x = t0 > 0.f ? t0 : al*t0;
            float t1 = v[1][s]; o.y = t1 > 0.f ? t1 : al*t1;
            float t2 = v[2][s]; o.z = t2 > 0.f ? t2 : al*t2;
            float t3 = v[3][s]; o.w = t3 > 0.f ? t3 : al*t3;
            *reinterpret_cast<float4*>(&g_h2[((bb*16 + oc)*PH + oy)*SP + x0]) = o;
        }
    }
}

// ============================================================
// K3F: winograd F(2,3)-x conv3 FILTER (decision-only).
// Thread pair (tid, tid^1) splits the 32 oc; each thread: 2 tiles
// (4 px) x 16 oc. Weights in SHARED (LDS.128, reuse 2x) -> FMA-bound.
// Appends pixels with approx logit > logit(0.6)-BAND to worklist.
// ============================================================
__global__ __launch_bounds__(256) void k3_filter(const float* __restrict__ b3,
                               const float* __restrict__ p3,
                               const float* __restrict__ w41, const float* __restrict__ b41)
{
    __shared__ __align__(16) ull swg[3072];   // [((c*3+ky)*4 + j)*16 + q]
    __shared__ float sbv[32], sp[32], sw41[64], sb41v[2];
    int tid = threadIdx.x;
    for (int i = tid; i < 3072; i += 256) swg[i] = g_stage[W3WOFF + i];
    if (tid < 32){ sbv[tid] = b3[tid]; sp[tid] = p3[tid]; }
    if (tid < 64) sw41[tid] = w41[tid];
    if (tid < 2)  sb41v[tid] = b41[tid];
    __syncthreads();

    int oc_half = tid & 1;            // 0: q 0-7 (oc 0-15), 1: q 8-15 (oc 16-31)
    int slot    = tid >> 1;           // 0..127
    int rowb    = slot >> 6;          // 0/1
    int xs      = slot & 63;          // 0..63
    int x0 = xs * 4;                  // 0..252; reads cols x0..x0+5 <= 257 < SP
    int oy = blockIdx.y * 2 + rowb;   // <= 187; reads rows oy..oy+2 <= 189 < PH
    int bb = blockIdx.z;
    int qbase = oc_half * 8;

    // m[tile][j][q]: winograd-domain accumulators; bias folded into m1
    ull m[2][4][8];
#pragma unroll
    for (int t = 0; t < 2; t++)
#pragma unroll
    for (int q = 0; q < 8; q++){
        int oc = 2*(qbase + q);
        m[t][0][q] = 0ULL;
        m[t][1][q] = pack2(sbv[oc], sbv[oc+1]);
        m[t][2][q] = 0ULL;
        m[t][3][q] = 0ULL;
    }

    for (int c = 0; c < 16; c++){
        const float* base = g_h2 + ((bb*16 + c)*PH + oy)*SP + x0;
#pragma unroll
        for (int ky = 0; ky < 3; ky++){
            float4 a4 = *reinterpret_cast<const float4*>(base + ky*SP);
            float2 b2 = *reinterpret_cast<const float2*>(base + ky*SP + 4);
            // tile0: d = (a4.x, a4.y, a4.z, a4.w); tile1: d = (a4.z, a4.w, b2.x, b2.y)
            float t00 = a4.x - a4.z, t01 = a4.y + a4.z, t02 = a4.z - a4.y, t03 = a4.y - a4.w;
            float t10 = a4.z - b2.x, t11 = a4.w + b2.x, t12 = b2.x - a4.w, t13 = a4.w - b2.y;
            ull p0[4], p1[4];
            p0[0] = pack2(t00,t00); p0[1] = pack2(t01,t01);
            p0[2] = pack2(t02,t02); p0[3] = pack2(t03,t03);
            p1[0] = pack2(t10,t10); p1[1] = pack2(t11,t11);
            p1[2] = pack2(t12,t12); p1[3] = pack2(t13,t13);
            const ull* wb = &swg[(c*3 + ky)*64 + qbase];
#pragma unroll
            for (int j = 0; j < 4; j++){
                const ulonglong2* wv2 = reinterpret_cast<const ulonglong2*>(wb + j*16);
                ull u0 = p0[j], u1 = p1[j];
#pragma unroll
                for (int g = 0; g < 4; g++){
                    ulonglong2 w2 = wv2[g];
                    fma2(m[0][j][2*g],   u0, w2.x);
                    fma2(m[0][j][2*g+1], u0, w2.y);
                    fma2(m[1][j][2*g],   u1, w2.x);
                    fma2(m[1][j][2*g+1], u1, w2.y);
                }
            }
        }
    }

    // combine + PReLU + score head over this thread's 16 oc; 4 px
    float bi0 = (oc_half == 0) ? sb41v[0] : 0.f;
    float bi1 = (oc_half == 0) ? sb41v[1] : 0.f;
    float l0s[4] = {bi0, bi0, bi0, bi0};
    float l1s[4] = {bi1, bi1, bi1, bi1};
#pragma unroll
    for (int t = 0; t < 2; t++)
#pragma unroll
    for (int q = 0; q < 8; q++){
        float m0l,m0h,m1l,m1h,m2l,m2h,m3l,m3h;
        unpack2(m[t][0][q], m0l, m0h);
        unpack2(m[t][1][q], m1l, m1h);
        unpack2(m[t][2][q], m2l, m2h);
        unpack2(m[t][3][q], m3l, m3h);
        float yAl = m0l + m1l + m2l;     // px 2t,   oc
        float yAh = m0h + m1h + m2h;     // px 2t,   oc+1
        float yBl = m1l - m2l - m3l;     // px 2t+1, oc
        float yBh = m1h - m2h - m3h;     // px 2t+1, oc+1
        int oc = 2*(qbase + q);
        float alo = sp[oc], ahi = sp[oc+1];
        yAl = yAl > 0.f ? yAl : alo*yAl;
        yAh = yAh > 0.f ? yAh : ahi*yAh;
        yBl = yBl > 0.f ? yBl : alo*yBl;
        yBh = yBh > 0.f ? yBh : ahi*yBh;
        float wA0 = sw41[oc],    wA1 = sw41[oc+1];
        float wB0 = sw41[32+oc], wB1 = sw41[32+oc+1];
        l0s[2*t]   = fmaf(yAl, wA0, fmaf(yAh, wA1, l0s[2*t]));
        l1s[2*t]   = fmaf(yAl, wB0, fmaf(yAh, wB1, l1s[2*t]));
        l0s[2*t+1] = fmaf(yBl, wA0, fmaf(yBh, wA1, l0s[2*t+1]));
        l1s[2*t+1] = fmaf(yBl, wB0, fmaf(yBh, wB1, l1s[2*t+1]));
    }
    // sum the two oc-halves (partner thread tid^1 has same 4 px)
#pragma unroll
    for (int px = 0; px < 4; px++){
        l0s[px] += __shfl_xor_sync(0xffffffffu, l0s[px], 1);
        l1s[px] += __shfl_xor_sync(0xffffffffu, l1s[px], 1);
    }
    if (oc_half == 0 && oy < H3D){
        const float thr = LOGIT06 - BAND;
#pragma unroll
        for (int px = 0; px < 4; px++){
            int x = x0 + px;
            if (x < W3D && (l1s[px] - l0s[px]) > thr){
                int pos = atomicAdd(&g_wcnt, 1);
                if (pos < BB*NPIX) g_work[pos] = (bb << 20) | (oy << 10) | x;
            }
        }
    }
}

// ============================================================
// K3B: exact conv3+heads at worklist pixels (R5-equivalent math).
// ============================================================
__global__ __launch_bounds__(128) void k3_exact(const float* __restrict__ b3,
                               const float* __restrict__ p3,
                               const float* __restrict__ w41, const float* __restrict__ b41,
                               const float* __restrict__ w42, const float* __restrict__ b42)
{
    __shared__ float sb[32], sp[32];
    __shared__ float sw41[64], sw42[128], sb41[2], sb42[4];
    int tid = threadIdx.x;
    if (tid < 32){ sb[tid] = b3[tid]; sp[tid] = p3[tid]; }
    if (tid < 64)  sw41[tid] = w41[tid];
    if (tid < 128) sw42[tid] = w42[tid];
    if (tid < 2)   sb41[tid] = b41[tid];
    if (tid < 4)   sb42[tid] = b42[tid];
    __syncthreads();

    int n = g_wcnt;
    if (n > BB*NPIX) n = BB*NPIX;

    for (int i = blockIdx.x * 128 + tid; i < n; i += gridDim.x * 128){
        int w = g_work[i];
        int x  = w & 1023;
        int y  = (w >> 10) & 1023;
        int bb = w >> 20;

        ull acc[16];
#pragma unroll
        for (int q = 0; q < 16; q++) acc[q] = pack2(sb[2*q], sb[2*q+1]);

        for (int c = 0; c < 16; c++){
            const float* base = g_h2 + ((bb*16 + c)*PH + y)*SP + x;
#pragma unroll
            for (int ky = 0; ky < 3; ky++){
                float v0 = base[ky*SP + 0];
                float v1 = base[ky*SP + 1];
                float v2 = base[ky*SP + 2];
                ull d0 = pack2(v0,v0), d1 = pack2(v1,v1), d2 = pack2(v2,v2);
                const ull* wq = &c_w3[(c*9 + ky*3)*16];
#pragma unroll
                for (int q = 0; q < 16; q++) fma2(acc[q], d0, wq[q]);
#pragma unroll
                for (int q = 0; q < 16; q++) fma2(acc[q], d1, wq[16+q]);
#pragma unroll
                for (int q = 0; q < 16; q++) fma2(acc[q], d2, wq[32+q]);
            }
        }

        float l0 = sb41[0], l1 = sb41[1];
        float r0 = sb42[0], r1 = sb42[1], r2 = sb42[2], r3 = sb42[3];
#pragma unroll
        for (int q = 0; q < 16; q++){
            float hA, hB; unpack2(acc[q], hA, hB);
            float alo = sp[2*q], ahi = sp[2*q+1];
            hA = hA > 0.f ? hA : alo*hA;
            hB = hB > 0.f ? hB : ahi*hB;
            float wA0 = sw41[2*q],    wA1 = sw41[2*q+1];
            float wB0 = sw41[32+2*q], wB1 = sw41[32+2*q+1];
            float q00 = sw42[2*q],    q01 = sw42[2*q+1];
            float q10 = sw42[32+2*q], q11 = sw42[32+2*q+1];
            float q20 = sw42[64+2*q], q21 = sw42[64+2*q+1];
            float q30 = sw42[96+2*q], q31 = sw42[96+2*q+1];
            l0 = fmaf(hA, wA0, fmaf(hB, wA1, l0));
            l1 = fmaf(hA, wB0, fmaf(hB, wB1, l1));
            r0 = fmaf(hA, q00, fmaf(hB, q01, r0));
            r1 = fmaf(hA, q10, fmaf(hB, q11, r1));
            r2 = fmaf(hA, q20, fmaf(hB, q21, r2));
            r3 = fmaf(hA, q30, fmaf(hB, q31, r3));
        }
        float prob = 1.f / (1.f + expf(l0 - l1));
        if (prob >= THRESH_V){
            int pos = atomicAdd(&g_cnt[bb], 1);
            if (pos < NPIX){
                g_cand[bb*NPIX + pos]    = (y << 16) | x;
                g_cand_sc[bb*NPIX + pos] = prob;
                g_cand_reg[bb*NPIX + pos] = make_float4(r0, r1, r2, r3);
            }
        }
    }
}

// ============================================================
// K4: per-batch iterative argmax NMS on unordered candidate list.
// Tie-break (score desc, packed xy asc) == pixel-index order.
// IoU>0.5 for 12x12 stride-2 boxes  <=>  |dx|<=1 && |dy|<=1.
// ============================================================
__global__ void k4_nms(float* __restrict__ out)
{
    const int NT = 256;
    int bb = blockIdx.x, tid = threadIdx.x;
    int lane = tid & 31, wrp = tid >> 5;

    __shared__ float s_sc[CAP];
    __shared__ int   s_xy[CAP];
    __shared__ float w_s[8];
    __shared__ int   w_xy[8], w_i[8];
    __shared__ float sh_best;
    __shared__ int   sh_j, sh_xy;

    int count = g_cnt[bb];
    if (count > NPIX) count = NPIX;
    bool insh = (count <= CAP);
    float* scp;
    const int* xyp;
    if (insh){
        for (int i = tid; i < count; i += NT){
            s_sc[i] = g_cand_sc[bb*NPIX + i];
            s_xy[i] = g_cand[bb*NPIX + i];
        }
        scp = s_sc; xyp = s_xy;
    } else {
        scp = g_cand_sc + bb*NPIX;
        xyp = g_cand + bb*NPIX;
    }
    __syncthreads();

    for (int k = 0; k < KPICKS; k++){
        float bs = -INFINITY; int bxy = 0x7fffffff; int bi = -1;
        for (int i = tid; i < count; i += NT){
            float v = scp[i]; int xy = xyp[i];
            if (v > bs || (v == bs && xy < bxy)){ bs = v; bxy = xy; bi = i; }
        }
#pragma unroll
        for (int off = 16; off > 0; off >>= 1){
            float vs  = __shfl_down_sync(0xffffffffu, bs,  off);
            int   vxy = __shfl_down_sync(0xffffffffu, bxy, off);
            int   vi  = __shfl_down_sync(0xffffffffu, bi,  off);
            if (vs > bs || (vs == bs && vxy < bxy)){ bs = vs; bxy = vxy; bi = vi; }
        }
        if (lane == 0){ w_s[wrp] = bs; w_xy[wrp] = bxy; w_i[wrp] = bi; }
        __syncthreads();
        if (tid == 0){
            float cs = w_s[0]; int cxy = w_xy[0], ci = w_i[0];
#pragma unroll
            for (int t = 1; t < 8; t++){
                if (w_s[t] > cs || (w_s[t] == cs && w_xy[t] < cxy)){
                    cs = w_s[t]; cxy = w_xy[t]; ci = w_i[t];
                }
            }
            sh_best = cs; sh_j = ci; sh_xy = cxy;
        }
        __syncthreads();
        float best = sh_best; int j = sh_j; int jxy = sh_xy;

        if (!(best > -0.5e30f) || j < 0){
            int n0 = (KPICKS - k) * 5;
            float* o0 = out + ((size_t)bb*KPICKS + k)*5;
            for (int t = tid; t < n0; t += NT) o0[t] = 0.f;
            break;
        }

        int jx = jxy & 0xffff, jy = jxy >> 16;
        for (int i = tid; i < count; i += NT){
            int p = xyp[i];
            int dx = (p & 0xffff) - jx; dx = dx < 0 ? -dx : dx;
            int dy = (p >> 16)    - jy; dy = dy < 0 ? -dy : dy;
            if (dx <= 1 && dy <= 1) scp[i] = NEGV;
        }
        if (tid == 0){
            float x1 = 2.f*jx + 1.f,  y1 = 2.f*jy + 1.f;
            float x2 = 2.f*jx + 12.f, y2 = 2.f*jy + 12.f;
            float4 r = g_cand_reg[bb*NPIX + j];
            float q1 = fmaf(r.x, 11.f, x1);
            float q2 = fmaf(r.y, 11.f, y1);
            float q3 = fmaf(r.z, 11.f, x2);
            float q4 = fmaf(r.w, 11.f, y2);
            float rw = q3 - q1, rh = q4 - q2;
            float l = fmaxf(rw, rh);
            float nx1 = q1 + rw*0.5f - l*0.5f;
            float ny1 = q2 + rh*0.5f - l*0.5f;
            float* o = out + ((size_t)bb*KPICKS + k)*5;
            o[0] = nx1; o[1] = ny1; o[2] = nx1 + l; o[3] = ny1 + l; o[4] = best;
        }
        __syncthreads();
    }
}

// ============================================================
extern "C" void kernel_launch(void* const* d_in, const int* in_sizes, int n_in,
                              void* d_out, int out_size)
{
    const float* im   = (const float*)d_in[0];
    const float* c1w  = (const float*)d_in[1];
    const float* c1b  = (const float*)d_in[2];
    const float* p1   = (const float*)d_in[3];
    const float* c2w  = (const float*)d_in[4];
    const float* c2b  = (const float*)d_in[5];
    const float* p2   = (const float*)d_in[6];
    const float* c3w  = (const float*)d_in[7];
    const float* c3b  = (const float*)d_in[8];
    const float* p3   = (const float*)d_in[9];
    const float* c41w = (const float*)d_in[10];
    const float* c41b = (const float*)d_in[11];
    const float* c42w = (const float*)d_in[12];
    const float* c42b = (const float*)d_in[13];
    float* out = (float*)d_out;

    // stage packed weights, then copy direct-path banks to constant
    k0_pack<<<1, 256>>>(c1w, c2w, c3w);
    void* stage_ptr = nullptr;
    cudaGetSymbolAddress(&stage_ptr, g_stage);
    const char* sp8 = (const char*)stage_ptr;
    cudaMemcpyToSymbolAsync(c_w1, sp8 + (size_t)W1OFF*8, (size_t)W1N*8, 0,
                            cudaMemcpyDeviceToDevice, 0);
    cudaMemcpyToSymbolAsync(c_w2, sp8 + (size_t)W2OFF*8, (size_t)W2N*8, 0,
                            cudaMemcpyDeviceToDevice, 0);
    cudaMemcpyToSymbolAsync(c_w3, sp8 + (size_t)W3OFF*8, (size_t)W3N*8, 0,
                            cudaMemcpyDeviceToDevice, 0);

    dim3 blk(32, 8, 1);
    dim3 g1(8, 24, BB);
    dim3 g2(2, 24, BB);

    dim3 gF(1, 94, BB);      // 94*2 rows cover 187 (+1 pad row); 64 slots * 4 px cover 251

    k1_conv1_pool<<<g1, blk>>>(im, c1b, p1);
    k2_conv2<<<g2, blk>>>(c2b, p2);
    k3_filter<<<gF, 256>>>(c3b, p3, c41w, c41b);
    k3_exact<<<592, 128>>>(c3b, p3, c41w, c41b, c42w, c42b);
    k4_nms<<<BB, 256>>>(out);
}

// round 11
// speedup vs baseline: 1.0603x; 1.0603x over previous
#include <cuda_runtime.h>
#include <math.h>

typedef unsigned long long ull;

// ---- problem constants ----
#define BB  16
#define HH  384
#define WW  512
#define HPP 191
#define WPP 255
#define H2D 189
#define W2D 253
#define H3D 187
#define W3D 251
#define NPIX (H3D*W3D)   // 46937
#define NEGV (-1e30f)
#define THRESH_V 0.6f
#define KPICKS 128
#define CAP 5600
#define SP  260          // padded row stride (mult of 4)
#define PH  196          // padded plane height

// logit(0.6) = ln(1.5); filter band 0.01 >> winograd fp32 error (~1e-5)
#define LOGIT06 0.40546510810816444f
#define BAND    0.01f

// staging layout offsets (in ull) — ALL EVEN so ulonglong2 (16B) loads
// from g_stage are aligned (g_stage itself is 16B-aligned).
#define W1OFF 0
#define W1N   135
#define W2OFF 136
#define W2N   720
#define W3OFF 856
#define W3N   2304
#define W3WOFF 3160
#define W3WN  3072
#define WTOT  6232

// ---- scratch (zero-initialized device globals) ----
__device__ __align__(16) float  g_pool[BB*10*PH*SP];
__device__ __align__(16) float  g_h2[BB*16*PH*SP];
__device__ __align__(16) ull    g_stage[WTOT];
__device__ int    g_cnt[BB];
__device__ int    g_wcnt;
__device__ int    g_work[BB*NPIX];      // packed (bb<<20)|(y<<10)|x
__device__ int    g_cand[BB*NPIX];      // packed (y<<16)|x
__device__ float  g_cand_sc[BB*NPIX];
__device__ float4 g_cand_reg[BB*NPIX];

// ---- packed oc-pair weights in constant memory (k1/k2: reuse 4x -> port OK) ----
__constant__ ull c_w1[W1N];    // [(c*9+k)*5  + q]
__constant__ ull c_w2[W2N];    // [(c*9+k)*8  + q]

// ---- f32x2 helpers ----
__device__ __forceinline__ ull pack2(float lo, float hi){
    ull r; asm("mov.b64 %0, {%1, %2};" : "=l"(r) : "f"(lo), "f"(hi)); return r;
}
__device__ __forceinline__ void unpack2(ull v, float &lo, float &hi){
    asm("mov.b64 {%0, %1}, %2;" : "=f"(lo), "=f"(hi) : "l"(v));
}
__device__ __forceinline__ void fma2(ull &d, ull a, ull b){
    asm("fma.rn.f32x2 %0, %1, %2, %0;" : "+l"(d) : "l"(a), "l"(b));
}

// ============================================================
// K0: pack weights (direct oc-pair + winograd) and zero counters
// ============================================================
__global__ void k0_pack(const float* __restrict__ w1,
                        const float* __restrict__ w2,
                        const float* __restrict__ w3)
{
    int tid = threadIdx.x;
    if (tid < BB) g_cnt[tid] = 0;
    if (tid == 0) g_wcnt = 0;
    for (int i = tid; i < W1N; i += 256){
        int ck = i / 5, q = i % 5;
        g_stage[W1OFF + i] = pack2(w1[(2*q)*27 + ck], w1[(2*q+1)*27 + ck]);
    }
    for (int i = tid; i < W2N; i += 256){
        int ck = i >> 3, q = i & 7;
        g_stage[W2OFF + i] = pack2(w2[(2*q)*90 + ck], w2[(2*q+1)*90 + ck]);
    }
    for (int i = tid; i < W3N; i += 256){
        int ck = i >> 4, q = i & 15;
        g_stage[W3OFF + i] = pack2(w3[(2*q)*144 + ck], w3[(2*q+1)*144 + ck]);
    }
    // winograd F(2,3) conv3 weights: g' = (g0, (g0+g1+g2)/2, (g0-g1+g2)/2, g2)
    // layout: [((c*3+ky)*4 + j)*16 + q]
    for (int i = tid; i < W3WN; i += 256){
        int q = i & 15;
        int t = i >> 4;
        int j = t & 3;
        int t2 = t >> 2;
        int ky = t2 % 3;
        int c  = t2 / 3;
        float v[2];
#pragma unroll
        for (int s = 0; s < 2; s++){
            int oc = 2*q + s;
            const float* g = w3 + oc*144 + c*9 + ky*3;
            float g0 = g[0], g1 = g[1], g2 = g[2];
            v[s] = (j == 0) ? g0
                 : (j == 1) ? 0.5f*(g0 + g1 + g2)
                 : (j == 2) ? 0.5f*(g0 - g1 + g2)
                 : g2;
        }
        g_stage[W3WOFF + i] = pack2(v[0], v[1]);
    }
}

// ============================================================
// K1: normalize + conv1(3x3,3->10) + PReLU + maxpool2x2  [R5]
// ============================================================
__global__ __launch_bounds__(256) void k1_conv1_pool(const float* __restrict__ im,
                              const float* __restrict__ b,
                              const float* __restrict__ p)
{
    __shared__ float sb[10], sp[10];
    int tid = threadIdx.y * 32 + threadIdx.x;
    if (tid < 10){ sb[tid] = b[tid]; sp[tid] = p[tid]; }
    __syncthreads();

    int ox = blockIdx.x * 32 + threadIdx.x;
    int oy = blockIdx.y * 8  + threadIdx.y;
    int bb = blockIdx.z;
    if (ox >= WPP || oy >= HPP) return;

    ull acc[4][5];
#pragma unroll
    for (int q = 0; q < 5; q++){
        ull bi = pack2(sb[2*q], sb[2*q+1]);
        acc[0][q] = bi; acc[1][q] = bi; acc[2][q] = bi; acc[3][q] = bi;
    }

#pragma unroll
    for (int c = 0; c < 3; c++){
        const float* base = im + ((bb*3 + c)*HH + 2*oy)*WW + 2*ox;
        ull du[4][4];
#pragma unroll
        for (int r = 0; r < 4; r++){
            float2 u01 = *reinterpret_cast<const float2*>(base + r*WW);
            float2 u23 = *reinterpret_cast<const float2*>(base + r*WW + 2);
            float v0 = (u01.x - 127.5f)*0.0078125f;
            float v1 = (u01.y - 127.5f)*0.0078125f;
            float v2 = (u23.x - 127.5f)*0.0078125f;
            float v3 = (u23.y - 127.5f)*0.0078125f;
            du[r][0] = pack2(v0,v0); du[r][1] = pack2(v1,v1);
            du[r][2] = pack2(v2,v2); du[r][3] = pack2(v3,v3);
        }
#pragma unroll
        for (int ky = 0; ky < 3; ky++)
#pragma unroll
        for (int kx = 0; kx < 3; kx++){
            const ull* wq = &c_w1[(c*9 + ky*3 + kx)*5];
#pragma unroll
            for (int q = 0; q < 5; q++){
                ull wv = wq[q];
                fma2(acc[0][q], du[ky  ][kx  ], wv);
                fma2(acc[1][q], du[ky  ][kx+1], wv);
                fma2(acc[2][q], du[ky+1][kx  ], wv);
                fma2(acc[3][q], du[ky+1][kx+1], wv);
            }
        }
    }
#pragma unroll
    for (int q = 0; q < 5; q++){
        float h[4][2];
#pragma unroll
        for (int pp = 0; pp < 4; pp++) unpack2(acc[pp][q], h[pp][0], h[pp][1]);
#pragma unroll
        for (int s = 0; s < 2; s++){
            int oc = 2*q + s;
            float al = sp[oc];
            float m = -INFINITY;
#pragma unroll
            for (int pp = 0; pp < 4; pp++){
                float v = h[pp][s];
                v = v > 0.f ? v : al*v;
                m = fmaxf(m, v);
            }
            g_pool[((bb*10 + oc)*PH + oy)*SP + ox] = m;
        }
    }
}

// ============================================================
// K2: conv2(3x3,10->16) + PReLU, 4 px/thread  [R5, exact]
// ============================================================
__global__ __launch_bounds__(256) void k2_conv2(const float* __restrict__ b,
                         const float* __restrict__ p)
{
    __shared__ float sb[16], sp[16];
    int tid = threadIdx.y * 32 + threadIdx.x;
    if (tid < 16){ sb[tid] = b[tid]; sp[tid] = p[tid]; }
    __syncthreads();

    int x0 = blockIdx.x * 128 + threadIdx.x * 4;
    int oy = blockIdx.y * 8   + threadIdx.y;
    int bb = blockIdx.z;

    ull acc[4][8];
#pragma unroll
    for (int q = 0; q < 8; q++){
        ull bi = pack2(sb[2*q], sb[2*q+1]);
        acc[0][q] = bi; acc[1][q] = bi; acc[2][q] = bi; acc[3][q] = bi;
    }

    for (int c = 0; c < 10; c++){
        const float* base = g_pool + ((bb*10 + c)*PH + oy)*SP + x0;
        ull du[3][6];
#pragma unroll
        for (int r = 0; r < 3; r++){
            float4 a4 = *reinterpret_cast<const float4*>(base + r*SP);
            float2 b2 = *reinterpret_cast<const float2*>(base + r*SP + 4);
            du[r][0] = pack2(a4.x,a4.x); du[r][1] = pack2(a4.y,a4.y);
            du[r][2] = pack2(a4.z,a4.z); du[r][3] = pack2(a4.w,a4.w);
            du[r][4] = pack2(b2.x,b2.x); du[r][5] = pack2(b2.y,b2.y);
        }
#pragma unroll
        for (int ky = 0; ky < 3; ky++)
#pragma unroll
        for (int kx = 0; kx < 3; kx++){
            const ull* wq = &c_w2[(c*9 + ky*3 + kx)*8];
#pragma unroll
            for (int q = 0; q < 8; q++){
                ull wv = wq[q];
#pragma unroll
                for (int pp = 0; pp < 4; pp++)
                    fma2(acc[pp][q], du[ky][kx+pp], wv);
            }
        }
    }
#pragma unroll
    for (int q = 0; q < 8; q++){
        float v[4][2];
#pragma unroll
        for (int pp = 0; pp < 4; pp++) unpack2(acc[pp][q], v[pp][0], v[pp][1]);
#pragma unroll
        for (int s = 0; s < 2; s++){
            int oc = 2*q + s;
            float al = sp[oc];
            float4 o;
            float t0 = v[0][s]; o.x = t0 > 0.f ? t0 : al*t0;
            float t1 = v[1][s]; o.y = t1 > 0.f ? t1 : al*t1;
            float t2 = v[2][s]; o.z = t2 > 0.f ? t2 : al*t2;
            float t3 = v[3][s]; o.w = t3 > 0.f ? t3 : al*t3;
            *reinterpret_cast<float4*>(&g_h2[((bb*16 + oc)*PH + oy)*SP + x0]) = o;
        }
    }
}

// ============================================================
// K3F: winograd F(2,3)-x conv3 FILTER (decision-only).
// 1 tile (2 px) x FULL 32 oc per thread; weights in SHARED
// (LDS.128, 1:2 vs FMA2 -> FMA-bound). Appends pixels with
// approx logit > logit(0.6)-BAND to worklist; values come
// from k3_exact only.
// ============================================================
__global__ __launch_bounds__(256) void k3_filter(const float* __restrict__ b3,
                               const float* __restrict__ p3,
                               const float* __restrict__ w41, const float* __restrict__ b41)
{
    __shared__ __align__(16) ull swg[3072];   // [((c*3+ky)*4 + j)*16 + q]
    __shared__ float sbv[32], sp[32], sw41[64], sb41v[2];
    int tid = threadIdx.y * 128 + threadIdx.x;
    {
        ulonglong2* d = reinterpret_cast<ulonglong2*>(swg);
        const ulonglong2* s = reinterpret_cast<const ulonglong2*>(&g_stage[W3WOFF]);
        for (int i = tid; i < 1536; i += 256) d[i] = s[i];
    }
    if (tid < 32){ sbv[tid] = b3[tid]; sp[tid] = p3[tid]; }
    if (tid < 64) sw41[tid] = w41[tid];
    if (tid < 2)  sb41v[tid] = b41[tid];
    __syncthreads();

    int x0 = threadIdx.x * 2;                  // 0..254; reads cols x0..x0+3 <= 257 < SP
    int oy = blockIdx.y * 2 + threadIdx.y;     // 0..187; reads rows oy..oy+2 <= 189 < PH
    int bb = blockIdx.z;

    // m[j][q]: winograd-domain accumulators; bias folded into m1
    // (y0 = m0+m1+m2, y1 = m1-m2-m3: m1 has +1 coeff in both).
    ull m[4][16];
#pragma unroll
    for (int q = 0; q < 16; q++){
        m[0][q] = 0ULL;
        m[1][q] = pack2(sbv[2*q], sbv[2*q+1]);
        m[2][q] = 0ULL;
        m[3][q] = 0ULL;
    }

    for (int c = 0; c < 16; c++){
        const float* base = g_h2 + ((bb*16 + c)*PH + oy)*SP + x0;
#pragma unroll
        for (int ky = 0; ky < 3; ky++){
            float2 a2 = *reinterpret_cast<const float2*>(base + ky*SP);
            float2 b2 = *reinterpret_cast<const float2*>(base + ky*SP + 2);
            float t0 = a2.x - b2.x;   // d0 - d2
            float t1 = a2.y + b2.x;   // d1 + d2
            float t2 = b2.x - a2.y;   // d2 - d1
            float t3 = a2.y - b2.y;   // d1 - d3
            ull pj[4];
            pj[0] = pack2(t0,t0); pj[1] = pack2(t1,t1);
            pj[2] = pack2(t2,t2); pj[3] = pack2(t3,t3);
            const ull* wb = &swg[(c*3 + ky)*64];
#pragma unroll
            for (int j = 0; j < 4; j++){
                const ulonglong2* wv2 = reinterpret_cast<const ulonglong2*>(wb + j*16);
                ull u = pj[j];
#pragma unroll
                for (int g = 0; g < 8; g++){
                    ulonglong2 w2 = wv2[g];
                    fma2(m[j][2*g],   u, w2.x);
                    fma2(m[j][2*g+1], u, w2.y);
                }
            }
        }
    }

    // combine + PReLU + score head (l1-l0) for both pixels
    float l0a = sb41v[0], l1a = sb41v[1];   // px x0
    float l0b = sb41v[0], l1b = sb41v[1];   // px x0+1
#pragma unroll
    for (int q = 0; q < 16; q++){
        float m0l,m0h,m1l,m1h,m2l,m2h,m3l,m3h;
        unpack2(m[0][q], m0l, m0h);
        unpack2(m[1][q], m1l, m1h);
        unpack2(m[2][q], m2l, m2h);
        unpack2(m[3][q], m3l, m3h);
        float yAl = m0l + m1l + m2l;      // px0, oc 2q
        float yAh = m0h + m1h + m2h;      // px0, oc 2q+1
        float yBl = m1l - m2l - m3l;      // px1, oc 2q
        float yBh = m1h - m2h - m3h;      // px1, oc 2q+1
        float alo = sp[2*q], ahi = sp[2*q+1];
        yAl = yAl > 0.f ? yAl : alo*yAl;
        yAh = yAh > 0.f ? yAh : ahi*yAh;
        yBl = yBl > 0.f ? yBl : alo*yBl;
        yBh = yBh > 0.f ? yBh : ahi*yBh;
        float wA0 = sw41[2*q],    wA1 = sw41[2*q+1];
        float wB0 = sw41[32+2*q], wB1 = sw41[32+2*q+1];
        l0a = fmaf(yAl, wA0, fmaf(yAh, wA1, l0a));
        l1a = fmaf(yAl, wB0, fmaf(yAh, wB1, l1a));
        l0b = fmaf(yBl, wA0, fmaf(yBh, wA1, l0b));
        l1b = fmaf(yBl, wB0, fmaf(yBh, wB1, l1b));
    }

    if (oy < H3D){
        const float thr = LOGIT06 - BAND;
        if (x0 < W3D && (l1a - l0a) > thr){
            int pos = atomicAdd(&g_wcnt, 1);
            if (pos < BB*NPIX) g_work[pos] = (bb << 20) | (oy << 10) | x0;
        }
        if (x0 + 1 < W3D && (l1b - l0b) > thr){
            int pos = atomicAdd(&g_wcnt, 1);
            if (pos < BB*NPIX) g_work[pos] = (bb << 20) | (oy << 10) | (x0 + 1);
        }
    }
}

// ============================================================
// K3B: exact conv3+heads at worklist pixels (R5-equivalent math).
// Weights in SHARED (avoids LDC half-rate port at reuse=1).
// ============================================================
__global__ __launch_bounds__(128) void k3_exact(const float* __restrict__ b3,
                               const float* __restrict__ p3,
                               const float* __restrict__ w41, const float* __restrict__ b41,
                               const float* __restrict__ w42, const float* __restrict__ b42)
{
    __shared__ __align__(16) ull sw3[2304];   // [(c*9+k)*16 + q]
    __shared__ float sb[32], sp[32];
    __shared__ float sw41[64], sw42[128], sb41[2], sb42[4];
    int tid = threadIdx.x;
    {
        ulonglong2* d = reinterpret_cast<ulonglong2*>(sw3);
        const ulonglong2* s = reinterpret_cast<const ulonglong2*>(&g_stage[W3OFF]);
        for (int i = tid; i < 1152; i += 128) d[i] = s[i];
    }
    if (tid < 32){ sb[tid] = b3[tid]; sp[tid] = p3[tid]; }
    if (tid < 64)  sw41[tid] = w41[tid];
    if (tid < 128) sw42[tid] = w42[tid];
    if (tid < 2)   sb41[tid] = b41[tid];
    if (tid < 4)   sb42[tid] = b42[tid];
    __syncthreads();

    int n = g_wcnt;
    if (n > BB*NPIX) n = BB*NPIX;

    for (int i = blockIdx.x * 128 + tid; i < n; i += gridDim.x * 128){
        int w = g_work[i];
        int x  = w & 1023;
        int y  = (w >> 10) & 1023;
        int bb = w >> 20;

        ull acc[16];
#pragma unroll
        for (int q = 0; q < 16; q++) acc[q] = pack2(sb[2*q], sb[2*q+1]);

        for (int c = 0; c < 16; c++){
            const float* base = g_h2 + ((bb*16 + c)*PH + y)*SP + x;
#pragma unroll
            for (int ky = 0; ky < 3; ky++){
                float v0 = base[ky*SP + 0];
                float v1 = base[ky*SP + 1];
                float v2 = base[ky*SP + 2];
                ull d0 = pack2(v0,v0), d1 = pack2(v1,v1), d2 = pack2(v2,v2);
                const ull* wq = &sw3[(c*9 + ky*3)*16];
#pragma unroll
                for (int q = 0; q < 16; q++) fma2(acc[q], d0, wq[q]);
#pragma unroll
                for (int q = 0; q < 16; q++) fma2(acc[q], d1, wq[16+q]);
#pragma unroll
                for (int q = 0; q < 16; q++) fma2(acc[q], d2, wq[32+q]);
            }
        }

        float l0 = sb41[0], l1 = sb41[1];
        float r0 = sb42[0], r1 = sb42[1], r2 = sb42[2], r3 = sb42[3];
#pragma unroll
        for (int q = 0; q < 16; q++){
            float hA, hB; unpack2(acc[q], hA, hB);
            float alo = sp[2*q], ahi = sp[2*q+1];
            hA = hA > 0.f ? hA : alo*hA;
            hB = hB > 0.f ? hB : ahi*hB;
            float wA0 = sw41[2*q],    wA1 = sw41[2*q+1];
            float wB0 = sw41[32+2*q], wB1 = sw41[32+2*q+1];
            float q00 = sw42[2*q],    q01 = sw42[2*q+1];
            float q10 = sw42[32+2*q], q11 = sw42[32+2*q+1];
            float q20 = sw42[64+2*q], q21 = sw42[64+2*q+1];
            float q30 = sw42[96+2*q], q31 = sw42[96+2*q+1];
            l0 = fmaf(hA, wA0, fmaf(hB, wA1, l0));
            l1 = fmaf(hA, wB0, fmaf(hB, wB1, l1));
            r0 = fmaf(hA, q00, fmaf(hB, q01, r0));
            r1 = fmaf(hA, q10, fmaf(hB, q11, r1));
            r2 = fmaf(hA, q20, fmaf(hB, q21, r2));
            r3 = fmaf(hA, q30, fmaf(hB, q31, r3));
        }
        float prob = 1.f / (1.f + expf(l0 - l1));
        if (prob >= THRESH_V){
            int pos = atomicAdd(&g_cnt[bb], 1);
            if (pos < NPIX){
                g_cand[bb*NPIX + pos]    = (y << 16) | x;
                g_cand_sc[bb*NPIX + pos] = prob;
                g_cand_reg[bb*NPIX + pos] = make_float4(r0, r1, r2, r3);
            }
        }
    }
}

// ============================================================
// K4: per-batch iterative argmax NMS on unordered candidate list.
// Tie-break (score desc, packed xy asc) == pixel-index order.
// IoU>0.5 for 12x12 stride-2 boxes  <=>  |dx|<=1 && |dy|<=1.
// ============================================================
__global__ void k4_nms(float* __restrict__ out)
{
    const int NT = 256;
    int bb = blockIdx.x, tid = threadIdx.x;
    int lane = tid & 31, wrp = tid >> 5;

    __shared__ float s_sc[CAP];
    __shared__ int   s_xy[CAP];
    __shared__ float w_s[8];
    __shared__ int   w_xy[8], w_i[8];
    __shared__ float sh_best;
    __shared__ int   sh_j, sh_xy;

    int count = g_cnt[bb];
    if (count > NPIX) count = NPIX;
    bool insh = (count <= CAP);
    float* scp;
    const int* xyp;
    if (insh){
        for (int i = tid; i < count; i += NT){
            s_sc[i] = g_cand_sc[bb*NPIX + i];
            s_xy[i] = g_cand[bb*NPIX + i];
        }
        scp = s_sc; xyp = s_xy;
    } else {
        scp = g_cand_sc + bb*NPIX;
        xyp = g_cand + bb*NPIX;
    }
    __syncthreads();

    for (int k = 0; k < KPICKS; k++){
        float bs = -INFINITY; int bxy = 0x7fffffff; int bi = -1;
        for (int i = tid; i < count; i += NT){
            float v = scp[i]; int xy = xyp[i];
            if (v > bs || (v == bs && xy < bxy)){ bs = v; bxy = xy; bi = i; }
        }
#pragma unroll
        for (int off = 16; off > 0; off >>= 1){
            float vs  = __shfl_down_sync(0xffffffffu, bs,  off);
            int   vxy = __shfl_down_sync(0xffffffffu, bxy, off);
            int   vi  = __shfl_down_sync(0xffffffffu, bi,  off);
            if (vs > bs || (vs == bs && vxy < bxy)){ bs = vs; bxy = vxy; bi = vi; }
        }
        if (lane == 0){ w_s[wrp] = bs; w_xy[wrp] = bxy; w_i[wrp] = bi; }
        __syncthreads();
        if (tid == 0){
            float cs = w_s[0]; int cxy = w_xy[0], ci = w_i[0];
#pragma unroll
            for (int t = 1; t < 8; t++){
                if (w_s[t] > cs || (w_s[t] == cs && w_xy[t] < cxy)){
                    cs = w_s[t]; cxy = w_xy[t]; ci = w_i[t];
                }
            }
            sh_best = cs; sh_j = ci; sh_xy = cxy;
        }
        __syncthreads();
        float best = sh_best; int j = sh_j; int jxy = sh_xy;

        if (!(best > -0.5e30f) || j < 0){
            int n0 = (KPICKS - k) * 5;
            float* o0 = out + ((size_t)bb*KPICKS + k)*5;
            for (int t = tid; t < n0; t += NT) o0[t] = 0.f;
            break;
        }

        int jx = jxy & 0xffff, jy = jxy >> 16;
        for (int i = tid; i < count; i += NT){
            int p = xyp[i];
            int dx = (p & 0xffff) - jx; dx = dx < 0 ? -dx : dx;
            int dy = (p >> 16)    - jy; dy = dy < 0 ? -dy : dy;
            if (dx <= 1 && dy <= 1) scp[i] = NEGV;
        }
        if (tid == 0){
            float x1 = 2.f*jx + 1.f,  y1 = 2.f*jy + 1.f;
            float x2 = 2.f*jx + 12.f, y2 = 2.f*jy + 12.f;
            float4 r = g_cand_reg[bb*NPIX + j];
            float q1 = fmaf(r.x, 11.f, x1);
            float q2 = fmaf(r.y, 11.f, y1);
            float q3 = fmaf(r.z, 11.f, x2);
            float q4 = fmaf(r.w, 11.f, y2);
            float rw = q3 - q1, rh = q4 - q2;
            float l = fmaxf(rw, rh);
            float nx1 = q1 + rw*0.5f - l*0.5f;
            float ny1 = q2 + rh*0.5f - l*0.5f;
            float* o = out + ((size_t)bb*KPICKS + k)*5;
            o[0] = nx1; o[1] = ny1; o[2] = nx1 + l; o[3] = ny1 + l; o[4] = best;
        }
        __syncthreads();
    }
}

// ============================================================
extern "C" void kernel_launch(void* const* d_in, const int* in_sizes, int n_in,
                              void* d_out, int out_size)
{
    const float* im   = (const float*)d_in[0];
    const float* c1w  = (const float*)d_in[1];
    const float* c1b  = (const float*)d_in[2];
    const float* p1   = (const float*)d_in[3];
    const float* c2w  = (const float*)d_in[4];
    const float* c2b  = (const float*)d_in[5];
    const float* p2   = (const float*)d_in[6];
    const float* c3w  = (const float*)d_in[7];
    const float* c3b  = (const float*)d_in[8];
    const float* p3   = (const float*)d_in[9];
    const float* c41w = (const float*)d_in[10];
    const float* c41b = (const float*)d_in[11];
    const float* c42w = (const float*)d_in[12];
    const float* c42b = (const float*)d_in[13];
    float* out = (float*)d_out;

    // stage packed weights; copy k1/k2 banks to constant (reuse 4x there)
    k0_pack<<<1, 256>>>(c1w, c2w, c3w);
    void* stage_ptr = nullptr;
    cudaGetSymbolAddress(&stage_ptr, g_stage);
    const char* sp8 = (const char*)stage_ptr;
    cudaMemcpyToSymbolAsync(c_w1, sp8 + (size_t)W1OFF*8, (size_t)W1N*8, 0,
                            cudaMemcpyDeviceToDevice, 0);
    cudaMemcpyToSymbolAsync(c_w2, sp8 + (size_t)W2OFF*8, (size_t)W2N*8, 0,
                            cudaMemcpyDeviceToDevice, 0);

    dim3 blk(32, 8, 1);
    dim3 g1(8, 24, BB);
    dim3 g2(2, 24, BB);

    dim3 blkF(128, 2, 1);
    dim3 gF(1, 94, BB);      // 94*2 rows cover 187 (+1 pad row); 128 tiles * 2px cover 251

    k1_conv1_pool<<<g1, blk>>>(im, c1b, p1);
    k2_conv2<<<g2, blk>>>(c2b, p2);
    k3_filter<<<gF, blkF>>>(c3b, p3, c41w, c41b);
    k3_exact<<<296, 128>>>(c3b, p3, c41w, c41b, c42w, c42b);
    k4_nms<<<BB, 256>>>(out);
}

// round 12
// speedup vs baseline: 1.5140x; 1.4279x over previous
#include <cuda_runtime.h>
#include <math.h>

typedef unsigned long long ull;

// ---- problem constants ----
#define BB  16
#define HH  384
#define WW  512
#define HPP 191
#define WPP 255
#define H2D 189
#define W2D 253
#define H3D 187
#define W3D 251
#define NPIX (H3D*W3D)   // 46937
#define NEGV (-1e30f)
#define THRESH_V 0.6f
#define KPICKS 128
#define CAP 5600
#define SP  260          // padded row stride (mult of 4)
#define PH  196          // padded plane height

// staging layout offsets (in ull) — ALL EVEN for aligned ulonglong2 loads
#define W1OFF 0
#define W1N   135
#define W2OFF 136
#define W2N   720
#define W3OFF 856
#define W3N   2304
#define WTOT  3160

// ---- scratch (zero-initialized device globals; padding deterministic) ----
__device__ __align__(16) float  g_pool[BB*10*PH*SP];
__device__ __align__(16) float  g_h2[BB*16*PH*SP];
__device__ __align__(16) ull    g_stage[WTOT];
__device__ int    g_cnt[BB];
__device__ int    g_cand[BB*NPIX];      // packed (y<<16)|x
__device__ float  g_cand_sc[BB*NPIX];
__device__ float4 g_cand_reg[BB*NPIX];

// ---- packed oc-pair weights in constant memory (reuse 4x -> port OK) ----
__constant__ ull c_w1[W1N];    // [(c*9+k)*5  + q]
__constant__ ull c_w2[W2N];    // [(c*9+k)*8  + q]
__constant__ ull c_w3[W3N];    // [(c*9+k)*16 + q]

// ---- f32x2 helpers ----
__device__ __forceinline__ ull pack2(float lo, float hi){
    ull r; asm("mov.b64 %0, {%1, %2};" : "=l"(r) : "f"(lo), "f"(hi)); return r;
}
__device__ __forceinline__ void unpack2(ull v, float &lo, float &hi){
    asm("mov.b64 {%0, %1}, %2;" : "=f"(lo), "=f"(hi) : "l"(v));
}
__device__ __forceinline__ void fma2(ull &d, ull a, ull b){
    asm("fma.rn.f32x2 %0, %1, %2, %0;" : "+l"(d) : "l"(a), "l"(b));
}

// ============================================================
// K0: pack weights into oc-pair layout + zero counters
// ============================================================
__global__ void k0_pack(const float* __restrict__ w1,
                        const float* __restrict__ w2,
                        const float* __restrict__ w3)
{
    int tid = threadIdx.x;
    if (tid < BB) g_cnt[tid] = 0;
    for (int i = tid; i < W1N; i += 256){
        int ck = i / 5, q = i % 5;
        g_stage[W1OFF + i] = pack2(w1[(2*q)*27 + ck], w1[(2*q+1)*27 + ck]);
    }
    for (int i = tid; i < W2N; i += 256){
        int ck = i >> 3, q = i & 7;
        g_stage[W2OFF + i] = pack2(w2[(2*q)*90 + ck], w2[(2*q+1)*90 + ck]);
    }
    for (int i = tid; i < W3N; i += 256){
        int ck = i >> 4, q = i & 15;
        g_stage[W3OFF + i] = pack2(w3[(2*q)*144 + ck], w3[(2*q+1)*144 + ck]);
    }
}

// ============================================================
// K1: normalize + conv1(3x3,3->10) + PReLU + maxpool2x2  [R5]
// ============================================================
__global__ __launch_bounds__(256) void k1_conv1_pool(const float* __restrict__ im,
                              const float* __restrict__ b,
                              const float* __restrict__ p)
{
    __shared__ float sb[10], sp[10];
    int tid = threadIdx.y * 32 + threadIdx.x;
    if (tid < 10){ sb[tid] = b[tid]; sp[tid] = p[tid]; }
    __syncthreads();

    int ox = blockIdx.x * 32 + threadIdx.x;
    int oy = blockIdx.y * 8  + threadIdx.y;
    int bb = blockIdx.z;
    if (ox >= WPP || oy >= HPP) return;

    ull acc[4][5];
#pragma unroll
    for (int q = 0; q < 5; q++){
        ull bi = pack2(sb[2*q], sb[2*q+1]);
        acc[0][q] = bi; acc[1][q] = bi; acc[2][q] = bi; acc[3][q] = bi;
    }

#pragma unroll
    for (int c = 0; c < 3; c++){
        const float* base = im + ((bb*3 + c)*HH + 2*oy)*WW + 2*ox;
        ull du[4][4];
#pragma unroll
        for (int r = 0; r < 4; r++){
            float2 u01 = *reinterpret_cast<const float2*>(base + r*WW);
            float2 u23 = *reinterpret_cast<const float2*>(base + r*WW + 2);
            float v0 = (u01.x - 127.5f)*0.0078125f;
            float v1 = (u01.y - 127.5f)*0.0078125f;
            float v2 = (u23.x - 127.5f)*0.0078125f;
            float v3 = (u23.y - 127.5f)*0.0078125f;
            du[r][0] = pack2(v0,v0); du[r][1] = pack2(v1,v1);
            du[r][2] = pack2(v2,v2); du[r][3] = pack2(v3,v3);
        }
#pragma unroll
        for (int ky = 0; ky < 3; ky++)
#pragma unroll
        for (int kx = 0; kx < 3; kx++){
            const ull* wq = &c_w1[(c*9 + ky*3 + kx)*5];
#pragma unroll
            for (int q = 0; q < 5; q++){
                ull wv = wq[q];
                fma2(acc[0][q], du[ky  ][kx  ], wv);
                fma2(acc[1][q], du[ky  ][kx+1], wv);
                fma2(acc[2][q], du[ky+1][kx  ], wv);
                fma2(acc[3][q], du[ky+1][kx+1], wv);
            }
        }
    }
#pragma unroll
    for (int q = 0; q < 5; q++){
        float h[4][2];
#pragma unroll
        for (int pp = 0; pp < 4; pp++) unpack2(acc[pp][q], h[pp][0], h[pp][1]);
#pragma unroll
        for (int s = 0; s < 2; s++){
            int oc = 2*q + s;
            float al = sp[oc];
            float m = -INFINITY;
#pragma unroll
            for (int pp = 0; pp < 4; pp++){
                float v = h[pp][s];
                v = v > 0.f ? v : al*v;
                m = fmaxf(m, v);
            }
            g_pool[((bb*10 + oc)*PH + oy)*SP + ox] = m;
        }
    }
}

// ============================================================
// K2: conv2(3x3,10->16) + PReLU, 4 px/thread  [R5 engine]
// block (32,4)=128 thr -> 2+ blocks/SM -> finer wave granularity
// ============================================================
__global__ __launch_bounds__(128) void k2_conv2(const float* __restrict__ b,
                         const float* __restrict__ p)
{
    __shared__ float sb[16], sp[16];
    int tid = threadIdx.y * 32 + threadIdx.x;
    if (tid < 16){ sb[tid] = b[tid]; sp[tid] = p[tid]; }
    __syncthreads();

    int x0 = blockIdx.x * 128 + threadIdx.x * 4;  // <= 252; reads <= 257 < SP
    int oy = blockIdx.y * 4   + threadIdx.y;      // <= 191; reads rows <= 193 < PH
    int bb = blockIdx.z;

    ull acc[4][8];
#pragma unroll
    for (int q = 0; q < 8; q++){
        ull bi = pack2(sb[2*q], sb[2*q+1]);
        acc[0][q] = bi; acc[1][q] = bi; acc[2][q] = bi; acc[3][q] = bi;
    }

    for (int c = 0; c < 10; c++){
        const float* base = g_pool + ((bb*10 + c)*PH + oy)*SP + x0;
        ull du[3][6];
#pragma unroll
        for (int r = 0; r < 3; r++){
            float4 a4 = *reinterpret_cast<const float4*>(base + r*SP);
            float2 b2 = *reinterpret_cast<const float2*>(base + r*SP + 4);
            du[r][0] = pack2(a4.x,a4.x); du[r][1] = pack2(a4.y,a4.y);
            du[r][2] = pack2(a4.z,a4.z); du[r][3] = pack2(a4.w,a4.w);
            du[r][4] = pack2(b2.x,b2.x); du[r][5] = pack2(b2.y,b2.y);
        }
#pragma unroll
        for (int ky = 0; ky < 3; ky++)
#pragma unroll
        for (int kx = 0; kx < 3; kx++){
            const ull* wq = &c_w2[(c*9 + ky*3 + kx)*8];
#pragma unroll
            for (int q = 0; q < 8; q++){
                ull wv = wq[q];
#pragma unroll
                for (int pp = 0; pp < 4; pp++)
                    fma2(acc[pp][q], du[ky][kx+pp], wv);
            }
        }
    }
#pragma unroll
    for (int q = 0; q < 8; q++){
        float v[4][2];
#pragma unroll
        for (int pp = 0; pp < 4; pp++) unpack2(acc[pp][q], v[pp][0], v[pp][1]);
#pragma unroll
        for (int s = 0; s < 2; s++){
            int oc = 2*q + s;
            float al = sp[oc];
            float4 o;
            float t0 = v[0][s]; o.x = t0 > 0.f ? t0 : al*t0;
            float t1 = v[1][s]; o.y = t1 > 0.f ? t1 : al*t1;
            float t2 = v[2][s]; o.z = t2 > 0.f ? t2 : al*t2;
            float t3 = v[3][s]; o.w = t3 > 0.f ? t3 : al*t3;
            *reinterpret_cast<float4*>(&g_h2[((bb*16 + oc)*PH + oy)*SP + x0]) = o;
        }
    }
}

// ============================================================
// K3: conv3(3x3,16->32)+PReLU + score head ONLY + append.
// R5 engine, 4 px/thread; reg head deferred to k3_regs for
// the ~1% of pixels that become candidates (l-chain identical
// to R5 since r-FMAs were independent of it).
// block (32,4)=128 thr -> 2 blocks/SM.
// ============================================================
__global__ __launch_bounds__(128) void k3_conv3_heads(const float* __restrict__ b3,
                               const float* __restrict__ p3,
                               const float* __restrict__ w41, const float* __restrict__ b41)
{
    __shared__ float sb[32], sp[32];
    __shared__ float sw41[64], sb41[2];
    int tid = threadIdx.y * 32 + threadIdx.x;
    if (tid < 32){ sb[tid] = b3[tid]; sp[tid] = p3[tid]; }
    if (tid < 64)  sw41[tid] = w41[tid];
    if (tid < 2)   sb41[tid] = b41[tid];
    __syncthreads();

    int x0 = blockIdx.x * 128 + threadIdx.x * 4;  // <= 252; reads <= 257 < SP
    int oy = blockIdx.y * 4   + threadIdx.y;      // <= 187; reads rows <= 189 < PH
    int bb = blockIdx.z;

    ull acc[4][16];
#pragma unroll
    for (int q = 0; q < 16; q++){
        ull bi = pack2(sb[2*q], sb[2*q+1]);
        acc[0][q] = bi; acc[1][q] = bi; acc[2][q] = bi; acc[3][q] = bi;
    }

    for (int c = 0; c < 16; c++){
        const float* base = g_h2 + ((bb*16 + c)*PH + oy)*SP + x0;
        ull du[3][6];
#pragma unroll
        for (int r = 0; r < 3; r++){
            float4 a4 = *reinterpret_cast<const float4*>(base + r*SP);
            float2 b2 = *reinterpret_cast<const float2*>(base + r*SP + 4);
            du[r][0] = pack2(a4.x,a4.x); du[r][1] = pack2(a4.y,a4.y);
            du[r][2] = pack2(a4.z,a4.z); du[r][3] = pack2(a4.w,a4.w);
            du[r][4] = pack2(b2.x,b2.x); du[r][5] = pack2(b2.y,b2.y);
        }
#pragma unroll
        for (int ky = 0; ky < 3; ky++)
#pragma unroll
        for (int kx = 0; kx < 3; kx++){
            const ull* wq = &c_w3[(c*9 + ky*3 + kx)*16];
#pragma unroll
            for (int q = 0; q < 16; q++){
                ull wv = wq[q];
#pragma unroll
                for (int pp = 0; pp < 4; pp++)
                    fma2(acc[pp][q], du[ky][kx+pp], wv);
            }
        }
    }

    // score head only (l chains identical to R5's — r-FMAs removed)
    float l0[4], l1[4];
#pragma unroll
    for (int pp = 0; pp < 4; pp++){ l0[pp] = sb41[0]; l1[pp] = sb41[1]; }
#pragma unroll
    for (int q = 0; q < 16; q++){
        float wA0 = sw41[2*q],    wA1 = sw41[2*q+1];
        float wB0 = sw41[32+2*q], wB1 = sw41[32+2*q+1];
        float alo = sp[2*q], ahi = sp[2*q+1];
#pragma unroll
        for (int pp = 0; pp < 4; pp++){
            float hA, hB; unpack2(acc[pp][q], hA, hB);
            hA = hA > 0.f ? hA : alo*hA;
            hB = hB > 0.f ? hB : ahi*hB;
            l0[pp] = fmaf(hA, wA0, fmaf(hB, wA1, l0[pp]));
            l1[pp] = fmaf(hA, wB0, fmaf(hB, wB1, l1[pp]));
        }
    }
    if (oy < H3D){
#pragma unroll
        for (int pp = 0; pp < 4; pp++){
            int x = x0 + pp;
            if (x >= W3D) continue;
            float prob = 1.f / (1.f + expf(l0[pp] - l1[pp]));
            if (prob >= THRESH_V){
                int pos = atomicAdd(&g_cnt[bb], 1);
                if (pos < NPIX){
                    g_cand[bb*NPIX + pos]    = (oy << 16) | x;
                    g_cand_sc[bb*NPIX + pos] = prob;
                }
            }
        }
    }
}

// ============================================================
// K3R: exact reg head for candidates only (~1% of pixels).
// Recomputes conv3 acc in the SAME (c,ky,kx,q) order as k3/R5
// (bitwise-identical accumulators) and fills g_cand_reg.
// Weights in SHARED (reuse=1 -> avoid LDC half-rate port).
// ============================================================
__global__ __launch_bounds__(128) void k3_regs(const float* __restrict__ b3,
                               const float* __restrict__ p3,
                               const float* __restrict__ w42, const float* __restrict__ b42)
{
    __shared__ __align__(16) ull sw3[2304];   // [(c*9+k)*16 + q]
    __shared__ float sb[32], sp[32];
    __shared__ float sw42[128], sb42[4];
    int tid = threadIdx.x;
    {
        ulonglong2* d = reinterpret_cast<ulonglong2*>(sw3);
        const ulonglong2* s = reinterpret_cast<const ulonglong2*>(&g_stage[W3OFF]);
        for (int i = tid; i < 1152; i += 128) d[i] = s[i];
    }
    if (tid < 32){ sb[tid] = b3[tid]; sp[tid] = p3[tid]; }
    if (tid < 128) sw42[tid] = w42[tid];
    if (tid < 4)   sb42[tid] = b42[tid];
    __syncthreads();

    int bb = blockIdx.y;
    int n = g_cnt[bb];
    if (n > NPIX) n = NPIX;

    for (int i = blockIdx.x * 128 + tid; i < n; i += gridDim.x * 128){
        int xy = g_cand[bb*NPIX + i];
        int x  = xy & 0xffff;
        int y  = xy >> 16;

        ull acc[16];
#pragma unroll
        for (int q = 0; q < 16; q++) acc[q] = pack2(sb[2*q], sb[2*q+1]);

        for (int c = 0; c < 16; c++){
            const float* base = g_h2 + ((bb*16 + c)*PH + y)*SP + x;
#pragma unroll
            for (int ky = 0; ky < 3; ky++){
                float v0 = base[ky*SP + 0];
                float v1 = base[ky*SP + 1];
                float v2 = base[ky*SP + 2];
                ull d0 = pack2(v0,v0), d1 = pack2(v1,v1), d2 = pack2(v2,v2);
                const ull* wq = &sw3[(c*9 + ky*3)*16];
#pragma unroll
                for (int q = 0; q < 16; q++) fma2(acc[q], d0, wq[q]);
#pragma unroll
                for (int q = 0; q < 16; q++) fma2(acc[q], d1, wq[16+q]);
#pragma unroll
                for (int q = 0; q < 16; q++) fma2(acc[q], d2, wq[32+q]);
            }
        }

        float r0 = sb42[0], r1 = sb42[1], r2 = sb42[2], r3 = sb42[3];
#pragma unroll
        for (int q = 0; q < 16; q++){
            float hA, hB; unpack2(acc[q], hA, hB);
            float alo = sp[2*q], ahi = sp[2*q+1];
            hA = hA > 0.f ? hA : alo*hA;
            hB = hB > 0.f ? hB : ahi*hB;
            float q00 = sw42[2*q],    q01 = sw42[2*q+1];
            float q10 = sw42[32+2*q], q11 = sw42[32+2*q+1];
            float q20 = sw42[64+2*q], q21 = sw42[64+2*q+1];
            float q30 = sw42[96+2*q], q31 = sw42[96+2*q+1];
            r0 = fmaf(hA, q00, fmaf(hB, q01, r0));
            r1 = fmaf(hA, q10, fmaf(hB, q11, r1));
            r2 = fmaf(hA, q20, fmaf(hB, q21, r2));
            r3 = fmaf(hA, q30, fmaf(hB, q31, r3));
        }
        g_cand_reg[bb*NPIX + i] = make_float4(r0, r1, r2, r3);
    }
}

// ============================================================
// K4: per-batch iterative argmax NMS on unordered candidate list.
// Tie-break (score desc, packed xy asc) == pixel-index order.
// IoU>0.5 for 12x12 stride-2 boxes  <=>  |dx|<=1 && |dy|<=1.
// ============================================================
__global__ void k4_nms(float* __restrict__ out)
{
    const int NT = 256;
    int bb = blockIdx.x, tid = threadIdx.x;
    int lane = tid & 31, wrp = tid >> 5;

    __shared__ float s_sc[CAP];
    __shared__ int   s_xy[CAP];
    __shared__ float w_s[8];
    __shared__ int   w_xy[8], w_i[8];
    __shared__ float sh_best;
    __shared__ int   sh_j, sh_xy;

    int count = g_cnt[bb];
    if (count > NPIX) count = NPIX;
    bool insh = (count <= CAP);
    float* scp;
    const int* xyp;
    if (insh){
        for (int i = tid; i < count; i += NT){
            s_sc[i] = g_cand_sc[bb*NPIX + i];
            s_xy[i] = g_cand[bb*NPIX + i];
        }
        scp = s_sc; xyp = s_xy;
    } else {
        scp = g_cand_sc + bb*NPIX;
        xyp = g_cand + bb*NPIX;
    }
    __syncthreads();

    for (int k = 0; k < KPICKS; k++){
        float bs = -INFINITY; int bxy = 0x7fffffff; int bi = -1;
        for (int i = tid; i < count; i += NT){
            float v = scp[i]; int xy = xyp[i];
            if (v > bs || (v == bs && xy < bxy)){ bs = v; bxy = xy; bi = i; }
        }
#pragma unroll
        for (int off = 16; off > 0; off >>= 1){
            float vs  = __shfl_down_sync(0xffffffffu, bs,  off);
            int   vxy = __shfl_down_sync(0xffffffffu, bxy, off);
            int   vi  = __shfl_down_sync(0xffffffffu, bi,  off);
            if (vs > bs || (vs == bs && vxy < bxy)){ bs = vs; bxy = vxy; bi = vi; }
        }
        if (lane == 0){ w_s[wrp] = bs; w_xy[wrp] = bxy; w_i[wrp] = bi; }
        __syncthreads();
        if (tid == 0){
            float cs = w_s[0]; int cxy = w_xy[0], ci = w_i[0];
#pragma unroll
            for (int t = 1; t < 8; t++){
                if (w_s[t] > cs || (w_s[t] == cs && w_xy[t] < cxy)){
                    cs = w_s[t]; cxy = w_xy[t]; ci = w_i[t];
                }
            }
            sh_best = cs; sh_j = ci; sh_xy = cxy;
        }
        __syncthreads();
        float best = sh_best; int j = sh_j; int jxy = sh_xy;

        if (!(best > -0.5e30f) || j < 0){
            int n0 = (KPICKS - k) * 5;
            float* o0 = out + ((size_t)bb*KPICKS + k)*5;
            for (int t = tid; t < n0; t += NT) o0[t] = 0.f;
            break;
        }

        int jx = jxy & 0xffff, jy = jxy >> 16;
        for (int i = tid; i < count; i += NT){
            int p = xyp[i];
            int dx = (p & 0xffff) - jx; dx = dx < 0 ? -dx : dx;
            int dy = (p >> 16)    - jy; dy = dy < 0 ? -dy : dy;
            if (dx <= 1 && dy <= 1) scp[i] = NEGV;
        }
        if (tid == 0){
            float x1 = 2.f*jx + 1.f,  y1 = 2.f*jy + 1.f;
            float x2 = 2.f*jx + 12.f, y2 = 2.f*jy + 12.f;
            float4 r = g_cand_reg[bb*NPIX + j];
            float q1 = fmaf(r.x, 11.f, x1);
            float q2 = fmaf(r.y, 11.f, y1);
            float q3 = fmaf(r.z, 11.f, x2);
            float q4 = fmaf(r.w, 11.f, y2);
            float rw = q3 - q1, rh = q4 - q2;
            float l = fmaxf(rw, rh);
            float nx1 = q1 + rw*0.5f - l*0.5f;
            float ny1 = q2 + rh*0.5f - l*0.5f;
            float* o = out + ((size_t)bb*KPICKS + k)*5;
            o[0] = nx1; o[1] = ny1; o[2] = nx1 + l; o[3] = ny1 + l; o[4] = best;
        }
        __syncthreads();
    }
}

// ============================================================
extern "C" void kernel_launch(void* const* d_in, const int* in_sizes, int n_in,
                              void* d_out, int out_size)
{
    const float* im   = (const float*)d_in[0];
    const float* c1w  = (const float*)d_in[1];
    const float* c1b  = (const float*)d_in[2];
    const float* p1   = (const float*)d_in[3];
    const float* c2w  = (const float*)d_in[4];
    const float* c2b  = (const float*)d_in[5];
    const float* p2   = (const float*)d_in[6];
    const float* c3w  = (const float*)d_in[7];
    const float* c3b  = (const float*)d_in[8];
    const float* p3   = (const float*)d_in[9];
    const float* c41w = (const float*)d_in[10];
    const float* c41b = (const float*)d_in[11];
    const float* c42w = (const float*)d_in[12];
    const float* c42b = (const float*)d_in[13];
    float* out = (float*)d_out;

    // stage packed weights; copy to constant banks (async D2D, capturable)
    k0_pack<<<1, 256>>>(c1w, c2w, c3w);
    void* stage_ptr = nullptr;
    cudaGetSymbolAddress(&stage_ptr, g_stage);
    const char* sp8 = (const char*)stage_ptr;
    cudaMemcpyToSymbolAsync(c_w1, sp8 + (size_t)W1OFF*8, (size_t)W1N*8, 0,
                            cudaMemcpyDeviceToDevice, 0);
    cudaMemcpyToSymbolAsync(c_w2, sp8 + (size_t)W2OFF*8, (size_t)W2N*8, 0,
                            cudaMemcpyDeviceToDevice, 0);
    cudaMemcpyToSymbolAsync(c_w3, sp8 + (size_t)W3OFF*8, (size_t)W3N*8, 0,
                            cudaMemcpyDeviceToDevice, 0);

    dim3 blk1(32, 8, 1);
    dim3 g1(8, 24, BB);

    dim3 blk2(32, 4, 1);
    dim3 g2(2, 48, BB);   // 48*4 rows cover 189 (+pad)
    dim3 g3(2, 47, BB);   // 47*4 rows cover 187 (+1 pad row)

    k1_conv1_pool<<<g1, blk1>>>(im, c1b, p1);
    k2_conv2<<<g2, blk2>>>(c2b, p2);
    k3_conv3_heads<<<g3, blk2>>>(c3b, p3, c41w, c41b);
    k3_regs<<<dim3(4, BB), 128>>>(c3b, p3, c42w, c42b);
    k4_nms<<<BB, 256>>>(out);
}